// round 1
// baseline (speedup 1.0000x reference)
#include <cuda_runtime.h>
#include <math.h>

// Problem constants
#define BB 4
#define NN 32768
#define KK 16
#define IN_DIM 32
#define HID 64
#define OUT_DIM 32
#define KIN 36
#define KH 64

// Scratch for pointwise-MLP output x: (B, N, 32) floats = 16 MB
__device__ float g_x[BB * NN * OUT_DIM];

__device__ __forceinline__ float gelu_exact(float v) {
    return 0.5f * v * (1.0f + erff(v * 0.7071067811865476f));
}

// ---------------------------------------------------------------------------
// Kernel 1: pointwise MLP  x = gelu(inp@Wp1+bp1)@Wp2+bp2   (one thread per (b,n))
// ---------------------------------------------------------------------------
__global__ __launch_bounds__(256) void pointwise_kernel(
    const float* __restrict__ inp,
    const float* __restrict__ Wp1, const float* __restrict__ bp1,
    const float* __restrict__ Wp2, const float* __restrict__ bp2)
{
    __shared__ float4 sW1[IN_DIM * HID / 4];   // 32x64 -> 512 float4
    __shared__ float4 sW2[HID * OUT_DIM / 4];  // 64x32 -> 512 float4
    __shared__ float  sB1[HID];
    __shared__ float  sB2[OUT_DIM];

    int tid = threadIdx.x;
    {
        const float4* g1 = (const float4*)Wp1;
        const float4* g2 = (const float4*)Wp2;
        for (int i = tid; i < IN_DIM * HID / 4; i += 256) sW1[i] = g1[i];
        for (int i = tid; i < HID * OUT_DIM / 4; i += 256) sW2[i] = g2[i];
        if (tid < HID) sB1[tid] = bp1[tid];
        if (tid < OUT_DIM) sB2[tid] = bp2[tid];
    }
    __syncthreads();

    int t = blockIdx.x * 256 + tid;   // 0 .. B*N-1
    const float4* ir = (const float4*)(inp + t * IN_DIM);

    float in[IN_DIM];
#pragma unroll
    for (int i = 0; i < IN_DIM / 4; ++i) {
        float4 v = ir[i];
        in[4*i+0] = v.x; in[4*i+1] = v.y; in[4*i+2] = v.z; in[4*i+3] = v.w;
    }

    float h[HID];
#pragma unroll
    for (int o4 = 0; o4 < HID / 4; ++o4) {
        float a0 = sB1[4*o4+0], a1 = sB1[4*o4+1], a2 = sB1[4*o4+2], a3 = sB1[4*o4+3];
#pragma unroll
        for (int c = 0; c < IN_DIM; ++c) {
            float4 w = sW1[c * (HID/4) + o4];
            float v = in[c];
            a0 = fmaf(v, w.x, a0); a1 = fmaf(v, w.y, a1);
            a2 = fmaf(v, w.z, a2); a3 = fmaf(v, w.w, a3);
        }
        h[4*o4+0] = gelu_exact(a0); h[4*o4+1] = gelu_exact(a1);
        h[4*o4+2] = gelu_exact(a2); h[4*o4+3] = gelu_exact(a3);
    }

    float4* xr = (float4*)(g_x + t * OUT_DIM);
#pragma unroll
    for (int o4 = 0; o4 < OUT_DIM / 4; ++o4) {
        float a0 = sB2[4*o4+0], a1 = sB2[4*o4+1], a2 = sB2[4*o4+2], a3 = sB2[4*o4+3];
#pragma unroll
        for (int c = 0; c < HID; ++c) {
            float4 w = sW2[c * (OUT_DIM/4) + o4];
            float v = h[c];
            a0 = fmaf(v, w.x, a0); a1 = fmaf(v, w.y, a1);
            a2 = fmaf(v, w.z, a2); a3 = fmaf(v, w.w, a3);
        }
        float4 r; r.x = a0; r.y = a1; r.z = a2; r.w = a3;
        xr[o4] = r;
    }
}

// ---------------------------------------------------------------------------
// Kernel 2: neighbor MLP + mean over K + residual + LayerNorm
// One thread per (b,n,k) edge. 16 lanes (half warp) = one node. Block = 8 nodes.
// ---------------------------------------------------------------------------
__global__ __launch_bounds__(128, 3) void edge_kernel(
    const float* __restrict__ igrid,   // (N,2)
    const float* __restrict__ ogrid,   // (N,2)
    const int*   __restrict__ nidx,    // (N,16)
    const float* __restrict__ Wk1, const float* __restrict__ bk1,
    const float* __restrict__ Wk2, const float* __restrict__ bk2,
    const float* __restrict__ Wk3, const float* __restrict__ bk3,
    const float* __restrict__ ln_g, const float* __restrict__ ln_b,
    float* __restrict__ out)
{
    __shared__ float4 sW1[KIN * KH / 4];      // 36x64 -> 576 float4 (9216 B)
    __shared__ float4 sW2[KH * KH / 4];       // 64x64 -> 1024 float4 (16384 B)
    __shared__ float4 sW3[KH * OUT_DIM / 4];  // 64x32 -> 512 float4 (8192 B)
    __shared__ float  sB1[KH], sB2[KH], sB3[OUT_DIM];
    __shared__ float  sG[OUT_DIM], sBt[OUT_DIM];

    int tid = threadIdx.x;
    {
        const float4* g1 = (const float4*)Wk1;
        const float4* g2 = (const float4*)Wk2;
        const float4* g3 = (const float4*)Wk3;
        for (int i = tid; i < KIN * KH / 4; i += 128) sW1[i] = g1[i];
        for (int i = tid; i < KH * KH / 4; i += 128) sW2[i] = g2[i];
        for (int i = tid; i < KH * OUT_DIM / 4; i += 128) sW3[i] = g3[i];
        if (tid < KH) { sB1[tid] = bk1[tid]; sB2[tid] = bk2[tid]; }
        if (tid < OUT_DIM) { sB3[tid] = bk3[tid]; sG[tid] = ln_g[tid]; sBt[tid] = ln_b[tid]; }
    }
    __syncthreads();

    int r = tid >> 4;           // node within block (0..7)
    int k = tid & 15;           // neighbor index (0..15)
    int bn = blockIdx.x * 8 + r;     // 0 .. B*N-1
    int b  = bn >> 15;               // / 32768
    int n  = bn & (NN - 1);

    int nb = nidx[n * KK + k];

    // agg = [input_grid[nb], output_grid[n], f_y(32)]
    float agg[KIN];
    agg[0] = igrid[nb * 2 + 0];
    agg[1] = igrid[nb * 2 + 1];
    agg[2] = ogrid[n * 2 + 0];
    agg[3] = ogrid[n * 2 + 1];
    {
        const float4* xr = (const float4*)(g_x + (b * NN + nb) * OUT_DIM);
#pragma unroll
        for (int i = 0; i < OUT_DIM / 4; ++i) {
            float4 v = xr[i];
            agg[4 + 4*i + 0] = v.x; agg[4 + 4*i + 1] = v.y;
            agg[4 + 4*i + 2] = v.z; agg[4 + 4*i + 3] = v.w;
        }
    }

    // Layer 1: 36 -> 64, gelu
    float h1[KH];
#pragma unroll
    for (int o4 = 0; o4 < KH / 4; ++o4) {
        float a0 = sB1[4*o4+0], a1 = sB1[4*o4+1], a2 = sB1[4*o4+2], a3 = sB1[4*o4+3];
#pragma unroll
        for (int c = 0; c < KIN; ++c) {
            float4 w = sW1[c * (KH/4) + o4];
            float v = agg[c];
            a0 = fmaf(v, w.x, a0); a1 = fmaf(v, w.y, a1);
            a2 = fmaf(v, w.z, a2); a3 = fmaf(v, w.w, a3);
        }
        h1[4*o4+0] = gelu_exact(a0); h1[4*o4+1] = gelu_exact(a1);
        h1[4*o4+2] = gelu_exact(a2); h1[4*o4+3] = gelu_exact(a3);
    }

    // Layer 2: 64 -> 64, gelu
    float h2[KH];
#pragma unroll
    for (int o4 = 0; o4 < KH / 4; ++o4) {
        float a0 = sB2[4*o4+0], a1 = sB2[4*o4+1], a2 = sB2[4*o4+2], a3 = sB2[4*o4+3];
#pragma unroll
        for (int c = 0; c < KH; ++c) {
            float4 w = sW2[c * (KH/4) + o4];
            float v = h1[c];
            a0 = fmaf(v, w.x, a0); a1 = fmaf(v, w.y, a1);
            a2 = fmaf(v, w.z, a2); a3 = fmaf(v, w.w, a3);
        }
        h2[4*o4+0] = gelu_exact(a0); h2[4*o4+1] = gelu_exact(a1);
        h2[4*o4+2] = gelu_exact(a2); h2[4*o4+3] = gelu_exact(a3);
    }

    // Layer 3: 64 -> 32, then reduce over K (16 lanes) via shfl butterfly
    float kout[OUT_DIM];
#pragma unroll
    for (int o4 = 0; o4 < OUT_DIM / 4; ++o4) {
        float a0 = sB3[4*o4+0], a1 = sB3[4*o4+1], a2 = sB3[4*o4+2], a3 = sB3[4*o4+3];
#pragma unroll
        for (int c = 0; c < KH; ++c) {
            float4 w = sW3[c * (OUT_DIM/4) + o4];
            float v = h2[c];
            a0 = fmaf(v, w.x, a0); a1 = fmaf(v, w.y, a1);
            a2 = fmaf(v, w.z, a2); a3 = fmaf(v, w.w, a3);
        }
#pragma unroll
        for (int off = 8; off >= 1; off >>= 1) {
            a0 += __shfl_xor_sync(0xffffffffu, a0, off);
            a1 += __shfl_xor_sync(0xffffffffu, a1, off);
            a2 += __shfl_xor_sync(0xffffffffu, a2, off);
            a3 += __shfl_xor_sync(0xffffffffu, a3, off);
        }
        kout[4*o4+0] = a0; kout[4*o4+1] = a1;
        kout[4*o4+2] = a2; kout[4*o4+3] = a3;
    }

    // Lane 0 of each 16-lane group: mean over K, residual, LayerNorm, store
    if (k == 0) {
        float o[OUT_DIM];
        const float4* xr = (const float4*)(g_x + bn * OUT_DIM);
        float sum = 0.0f;
#pragma unroll
        for (int i = 0; i < OUT_DIM / 4; ++i) {
            float4 v = xr[i];
            o[4*i+0] = fmaf(kout[4*i+0], 0.0625f, v.x);
            o[4*i+1] = fmaf(kout[4*i+1], 0.0625f, v.y);
            o[4*i+2] = fmaf(kout[4*i+2], 0.0625f, v.z);
            o[4*i+3] = fmaf(kout[4*i+3], 0.0625f, v.w);
            sum += o[4*i+0] + o[4*i+1] + o[4*i+2] + o[4*i+3];
        }
        float mu = sum * (1.0f / OUT_DIM);
        float vs = 0.0f;
#pragma unroll
        for (int i = 0; i < OUT_DIM; ++i) {
            float d = o[i] - mu;
            vs = fmaf(d, d, vs);
        }
        float rs = rsqrtf(vs * (1.0f / OUT_DIM) + 1e-5f);

        float4* op = (float4*)(out + bn * OUT_DIM);
#pragma unroll
        for (int i = 0; i < OUT_DIM / 4; ++i) {
            float4 w;
            w.x = fmaf((o[4*i+0] - mu) * rs, sG[4*i+0], sBt[4*i+0]);
            w.y = fmaf((o[4*i+1] - mu) * rs, sG[4*i+1], sBt[4*i+1]);
            w.z = fmaf((o[4*i+2] - mu) * rs, sG[4*i+2], sBt[4*i+2]);
            w.w = fmaf((o[4*i+3] - mu) * rs, sG[4*i+3], sBt[4*i+3]);
            op[i] = w;
        }
    }
}

// ---------------------------------------------------------------------------
extern "C" void kernel_launch(void* const* d_in, const int* in_sizes, int n_in,
                              void* d_out, int out_size) {
    const float* inp   = (const float*)d_in[0];
    const float* igrid = (const float*)d_in[1];
    const float* ogrid = (const float*)d_in[2];
    const int*   nidx  = (const int*)  d_in[3];
    const float* Wp1   = (const float*)d_in[4];
    const float* bp1   = (const float*)d_in[5];
    const float* Wp2   = (const float*)d_in[6];
    const float* bp2   = (const float*)d_in[7];
    const float* Wk1   = (const float*)d_in[8];
    const float* bk1   = (const float*)d_in[9];
    const float* Wk2   = (const float*)d_in[10];
    const float* bk2   = (const float*)d_in[11];
    const float* Wk3   = (const float*)d_in[12];
    const float* bk3   = (const float*)d_in[13];
    const float* ln_g  = (const float*)d_in[14];
    const float* ln_b  = (const float*)d_in[15];
    float* out = (float*)d_out;

    pointwise_kernel<<<(BB * NN) / 256, 256>>>(inp, Wp1, bp1, Wp2, bp2);
    edge_kernel<<<(BB * NN) / 8, 128>>>(igrid, ogrid, nidx,
                                        Wk1, bk1, Wk2, bk2, Wk3, bk3,
                                        ln_g, ln_b, out);
}